// round 1
// baseline (speedup 1.0000x reference)
#include <cuda_runtime.h>

#define SPECIES 4
#define POP     4096
#define DIM     16
#define NTOT    (SPECIES * POP)      // 16384
#define JSPLIT  8
#define JCHUNK  (POP / JSPLIT)       // 512
#define IBLOCK  256
#define NSTEPS  4

#define LBV (-4.0f)
#define UBV (4.0f)

// ---------------- device scratch (no allocations allowed) ----------------
__device__ float g_xA[NTOT * DIM];
__device__ float g_xB[NTOT * DIM];
__device__ float g_sq[NTOT];
__device__ float g_cost[NTOT];
// partial accumulators: [jsplit][17][NTOT]  (16 dims of sum(w*xj) + wsum)
__device__ float g_part[JSPLIT * 17 * NTOT];

// ---------------- f32x2 helpers (Blackwell packed fp32 FMA) ----------------
__device__ __forceinline__ unsigned long long pack2(float lo, float hi) {
    unsigned long long r;
    asm("mov.b64 %0, {%1, %2};" : "=l"(r) : "f"(lo), "f"(hi));
    return r;
}
__device__ __forceinline__ void unpack2(unsigned long long v, float& lo, float& hi) {
    asm("mov.b64 {%0, %1}, %2;" : "=f"(lo), "=f"(hi) : "l"(v));
}
#define FMA2(d, a, b, c) \
    asm("fma.rn.f32x2 %0, %1, %2, %3;" : "=l"(d) : "l"(a), "l"(b), "l"(c))
#define MUL2(d, a, b) \
    asm("mul.rn.f32x2 %0, %1, %2;" : "=l"(d) : "l"(a), "l"(b))

// ---------------- prep: copy input, compute sq + rastrigin cost ----------------
__global__ void prep_kernel(const float* __restrict__ fireflies) {
    int idx = blockIdx.x * blockDim.x + threadIdx.x;  // (s,p) flattened
    if (idx >= NTOT) return;
    const float4* src = reinterpret_cast<const float4*>(fireflies + idx * DIM);
    float4* dst = reinterpret_cast<float4*>(g_xA + idx * DIM);
    float sq = 0.0f;
    float cost = 10.0f * (float)DIM;
#pragma unroll
    for (int q = 0; q < 4; ++q) {
        float4 v = src[q];
        dst[q] = v;
        float xs[4] = {v.x, v.y, v.z, v.w};
#pragma unroll
        for (int e = 0; e < 4; ++e) {
            float xv = xs[e];
            sq = fmaf(xv, xv, sq);
            cost += xv * xv - 10.0f * cosf(6.283185307179586f * xv);
        }
    }
    g_sq[idx] = sq;
    g_cost[idx] = cost;
}

// ---------------- pairwise: partial attraction accumulators ----------------
// grid: (POP/IBLOCK, JSPLIT, SPECIES), block: IBLOCK threads (one firefly i each)
__global__ __launch_bounds__(IBLOCK) void pairwise_kernel(const float* __restrict__ x) {
    __shared__ float  s_x[JCHUNK * DIM];   // 32 KB
    __shared__ float2 s_sc[JCHUNK];        // (sq_j, cost_j) 4 KB

    const int s  = blockIdx.z;
    const int i  = s * POP + blockIdx.x * IBLOCK + threadIdx.x;
    const int j0 = s * POP + blockIdx.y * JCHUNK;

    // cooperative stage of the j-chunk
    {
        const float4* src = reinterpret_cast<const float4*>(x + j0 * DIM);
        float4* dst = reinterpret_cast<float4*>(s_x);
#pragma unroll
        for (int t = threadIdx.x; t < (JCHUNK * DIM) / 4; t += IBLOCK)
            dst[t] = src[t];
        for (int t = threadIdx.x; t < JCHUNK; t += IBLOCK)
            s_sc[t] = make_float2(g_sq[j0 + t], g_cost[j0 + t]);
    }
    __syncthreads();

    // per-thread firefly i state (packed f32x2)
    unsigned long long xi[8];
    {
        const ulonglong2* xp = reinterpret_cast<const ulonglong2*>(x + i * DIM);
#pragma unroll
        for (int q = 0; q < 4; ++q) {
            ulonglong2 v = xp[q];
            xi[2 * q]     = v.x;
            xi[2 * q + 1] = v.y;
        }
    }
    const float sqi = g_sq[i];
    const float ci  = g_cost[i];

    unsigned long long acc[8];
    const unsigned long long zero2 = pack2(0.0f, 0.0f);
#pragma unroll
    for (int q = 0; q < 8; ++q) acc[q] = zero2;
    float wsum = 0.0f;

#pragma unroll 2
    for (int jj = 0; jj < JCHUNK; ++jj) {
        const ulonglong2* xjv = reinterpret_cast<const ulonglong2*>(s_x + jj * DIM);
        ulonglong2 va = xjv[0];
        ulonglong2 vb = xjv[1];
        ulonglong2 vc = xjv[2];
        ulonglong2 vd = xjv[3];

        // dot(xi, xj): two independent chains for ILP
        unsigned long long dp0, dp1;
        MUL2(dp0, xi[0], va.x);
        MUL2(dp1, xi[1], va.y);
        FMA2(dp0, xi[2], vb.x, dp0);
        FMA2(dp1, xi[3], vb.y, dp1);
        FMA2(dp0, xi[4], vc.x, dp0);
        FMA2(dp1, xi[5], vc.y, dp1);
        FMA2(dp0, xi[6], vd.x, dp0);
        FMA2(dp1, xi[7], vd.y, dp1);

        float a0, a1, b0, b1;
        unpack2(dp0, a0, a1);
        unpack2(dp1, b0, b1);
        float dot = (a0 + a1) + (b0 + b1);

        float2 sc = s_sc[jj];
        float d2 = fmaxf(fmaf(dot, -2.0f, sqi + sc.x), 0.0f);

        // w = BETA0 * exp(-d2)  == exp2(1 - d2*log2(e)), masked by cost_i > cost_j
        float targ = fmaf(d2, -1.44269504088896340736f, 1.0f);
        float w;
        asm("ex2.approx.f32 %0, %1;" : "=f"(w) : "f"(targ));
        w = (ci > sc.y) ? w : 0.0f;

        unsigned long long w2 = pack2(w, w);
        FMA2(acc[0], w2, va.x, acc[0]);
        FMA2(acc[1], w2, va.y, acc[1]);
        FMA2(acc[2], w2, vb.x, acc[2]);
        FMA2(acc[3], w2, vb.y, acc[3]);
        FMA2(acc[4], w2, vc.x, acc[4]);
        FMA2(acc[5], w2, vc.y, acc[5]);
        FMA2(acc[6], w2, vd.x, acc[6]);
        FMA2(acc[7], w2, vd.y, acc[7]);
        wsum += w;
    }

    // write partials: g_part[jsplit][c][i]
    float* base = g_part + (size_t)blockIdx.y * 17 * NTOT;
#pragma unroll
    for (int q = 0; q < 8; ++q) {
        float lo, hi;
        unpack2(acc[q], lo, hi);
        base[(2 * q) * NTOT + i]     = lo;
        base[(2 * q + 1) * NTOT + i] = hi;
    }
    base[16 * NTOT + i] = wsum;
}

// ---------------- update: reduce partials, walk, clip, mix, recompute cost ----------------
__global__ void update_kernel(const float* __restrict__ xin,
                              float* __restrict__ xout,
                              const float* __restrict__ noise_step,
                              float alpha, int do_mix) {
    int idx = blockIdx.x * blockDim.x + threadIdx.x;
    if (idx >= NTOT) return;
    int s = idx / POP;
    int p = idx % POP;

    int ds = (do_mix && p >= POP / 2) ? ((s + 1) & (SPECIES - 1)) : s;
    int didx = ds * POP + p;

    // wsum
    float ws = 0.0f;
#pragma unroll
    for (int k = 0; k < JSPLIT; ++k)
        ws += g_part[((size_t)k * 17 + 16) * NTOT + idx];

    float sq = 0.0f;
    float cost = 10.0f * (float)DIM;
    const float scale = alpha * (UBV - LBV);

#pragma unroll
    for (int d = 0; d < DIM; ++d) {
        float a = 0.0f;
#pragma unroll
        for (int k = 0; k < JSPLIT; ++k)
            a += g_part[((size_t)k * 17 + d) * NTOT + idx];
        float xv = xin[idx * DIM + d];
        float rw = scale * (noise_step[idx * DIM + d] - 0.5f);
        float xn = xv + (a - ws * xv) + rw;
        xn = fminf(fmaxf(xn, LBV), UBV);
        xout[didx * DIM + d] = xn;
        sq = fmaf(xn, xn, sq);
        cost += xn * xn - 10.0f * cosf(6.283185307179586f * xn);
    }
    g_sq[didx] = sq;
    g_cost[didx] = cost;
}

// ---------------- launch ----------------
extern "C" void kernel_launch(void* const* d_in, const int* in_sizes, int n_in,
                              void* d_out, int out_size) {
    const float* fireflies = (const float*)d_in[0];
    const float* noise     = (const float*)d_in[1];
    float* out = (float*)d_out;

    float *xA, *xB;
    cudaGetSymbolAddress((void**)&xA, g_xA);
    cudaGetSymbolAddress((void**)&xB, g_xB);

    dim3 pw_grid(POP / IBLOCK, JSPLIT, SPECIES);
    int up_blocks = NTOT / 256;

    prep_kernel<<<up_blocks, 256>>>(fireflies);

    double alpha = 0.1;
    float* bufs[2] = {xA, xB};
    const float* cur = xA;
    for (int step = 0; step < NSTEPS; ++step) {
        pairwise_kernel<<<pw_grid, IBLOCK>>>(cur);
        float* dst = (step == NSTEPS - 1) ? out : bufs[(step + 1) & 1];
        const float* nz = noise + (size_t)step * NTOT * DIM;
        int do_mix = (step % 25 == 0) ? 1 : 0;
        update_kernel<<<up_blocks, 256>>>(cur, dst, nz, (float)alpha, do_mix);
        alpha *= 0.995;
        cur = dst;
    }
}

// round 2
// speedup vs baseline: 1.0239x; 1.0239x over previous
#include <cuda_runtime.h>

#define SPECIES 4
#define POP     4096
#define DIM     16
#define NTOT    (SPECIES * POP)      // 16384
#define IBLOCK  128
#define JCHUNK  256
#define JSPLIT  (POP / JCHUNK)       // 16
#define NSTEPS  4

#define LBV (-4.0f)
#define UBV (4.0f)
#define LOG2E 1.44269504088896340736f

// ---------------- device scratch (no allocations allowed) ----------------
__device__ float  g_xA[NTOT * DIM];     // original-order positions
__device__ float  g_xS[NTOT * DIM];     // sorted-order positions
__device__ float  g_sq[NTOT];           // |x|^2, original order
__device__ float  g_cost[NTOT];         // rastrigin cost, original order
__device__ int    g_perm[NTOT];         // sorted slot -> original p (within species)
__device__ float2 g_scS[NTOT];          // sorted: (-LOG2E*sq, cost)
// partials: [jsplit][17][NTOT]  (16 dims of sum(w*xj) + wsum), sorted index
__device__ float  g_part[JSPLIT * 17 * NTOT];

// ---------------- f32x2 helpers ----------------
__device__ __forceinline__ unsigned long long pack2(float lo, float hi) {
    unsigned long long r;
    asm("mov.b64 %0, {%1, %2};" : "=l"(r) : "f"(lo), "f"(hi));
    return r;
}
__device__ __forceinline__ void unpack2(unsigned long long v, float& lo, float& hi) {
    asm("mov.b64 {%0, %1}, %2;" : "=f"(lo), "=f"(hi) : "l"(v));
}
#define FMA2(d, a, b, c) \
    asm("fma.rn.f32x2 %0, %1, %2, %3;" : "=l"(d) : "l"(a), "l"(b), "l"(c))
#define MUL2(d, a, b) \
    asm("mul.rn.f32x2 %0, %1, %2;" : "=l"(d) : "l"(a), "l"(b))

// ---------------- prep: copy input, compute sq + rastrigin cost ----------------
__global__ void prep_kernel(const float* __restrict__ fireflies) {
    int idx = blockIdx.x * blockDim.x + threadIdx.x;
    if (idx >= NTOT) return;
    const float4* src = reinterpret_cast<const float4*>(fireflies + idx * DIM);
    float4* dst = reinterpret_cast<float4*>(g_xA + idx * DIM);
    float sq = 0.0f;
    float cost = 10.0f * (float)DIM;
#pragma unroll
    for (int q = 0; q < 4; ++q) {
        float4 v = src[q];
        dst[q] = v;
        float xs[4] = {v.x, v.y, v.z, v.w};
#pragma unroll
        for (int e = 0; e < 4; ++e) {
            float xv = xs[e];
            sq = fmaf(xv, xv, sq);
            cost += xv * xv - 10.0f * cosf(6.283185307179586f * xv);
        }
    }
    g_sq[idx] = sq;
    g_cost[idx] = cost;
}

// ---------------- per-species bitonic sort by cost (ascending) ----------------
__global__ __launch_bounds__(1024) void sort_kernel() {
    __shared__ float skey[POP];
    __shared__ int   sidx[POP];
    const int s = blockIdx.x;
    for (int t = threadIdx.x; t < POP; t += 1024) {
        skey[t] = g_cost[s * POP + t];
        sidx[t] = t;
    }
    __syncthreads();
    for (int k = 2; k <= POP; k <<= 1) {
        for (int j = k >> 1; j > 0; j >>= 1) {
            for (int t = threadIdx.x; t < POP; t += 1024) {
                int ixj = t ^ j;
                if (ixj > t) {
                    bool up = ((t & k) == 0);
                    float a = skey[t], b = skey[ixj];
                    if ((a > b) == up) {
                        skey[t] = b; skey[ixj] = a;
                        int tmp = sidx[t]; sidx[t] = sidx[ixj]; sidx[ixj] = tmp;
                    }
                }
            }
            __syncthreads();
        }
    }
    for (int t = threadIdx.x; t < POP; t += 1024)
        g_perm[s * POP + t] = sidx[t];
}

// ---------------- gather into sorted order ----------------
__global__ void gather_kernel() {
    int r = blockIdx.x * blockDim.x + threadIdx.x;
    if (r >= NTOT) return;
    int s = r / POP;
    int orig = s * POP + g_perm[r];
    const float4* src = reinterpret_cast<const float4*>(g_xA + orig * DIM);
    float4* dst = reinterpret_cast<float4*>(g_xS + r * DIM);
#pragma unroll
    for (int q = 0; q < 4; ++q) dst[q] = src[q];
    g_scS[r] = make_float2(-LOG2E * g_sq[orig], g_cost[orig]);
}

// ---------------- pairwise on sorted order, lower-triangle blocks only ----------------
// grid: (POP/IBLOCK, JSPLIT, SPECIES), block: IBLOCK
__global__ __launch_bounds__(IBLOCK) void pairwise_kernel() {
    // all j-ranks in this chunk exceed all i-ranks -> every pair masked off
    if (blockIdx.y * JCHUNK > blockIdx.x * IBLOCK + (IBLOCK - 1)) return;

    __shared__ float  s_x[JCHUNK * DIM];   // 16 KB
    __shared__ float2 s_sc[JCHUNK];        // 2 KB

    const int s  = blockIdx.z;
    const int i  = s * POP + blockIdx.x * IBLOCK + threadIdx.x;
    const int j0 = s * POP + blockIdx.y * JCHUNK;

    {
        const float4* src = reinterpret_cast<const float4*>(g_xS + j0 * DIM);
        float4* dst = reinterpret_cast<float4*>(s_x);
#pragma unroll
        for (int t = threadIdx.x; t < (JCHUNK * DIM) / 4; t += IBLOCK)
            dst[t] = src[t];
        for (int t = threadIdx.x; t < JCHUNK; t += IBLOCK)
            s_sc[t] = g_scS[j0 + t];
    }
    __syncthreads();

    unsigned long long xi[8];
    {
        const ulonglong2* xp = reinterpret_cast<const ulonglong2*>(g_xS + i * DIM);
#pragma unroll
        for (int q = 0; q < 4; ++q) {
            ulonglong2 v = xp[q];
            xi[2 * q]     = v.x;
            xi[2 * q + 1] = v.y;
        }
    }
    const float2 sci = g_scS[i];
    const float ai = 1.0f + sci.x;   // log2(BETA0) - LOG2E*sq_i
    const float ci = sci.y;

    unsigned long long acc[8];
    const unsigned long long zero2 = pack2(0.0f, 0.0f);
#pragma unroll
    for (int q = 0; q < 8; ++q) acc[q] = zero2;
    float wsum = 0.0f;

#pragma unroll 2
    for (int jj = 0; jj < JCHUNK; ++jj) {
        const ulonglong2* xjv = reinterpret_cast<const ulonglong2*>(s_x + jj * DIM);
        ulonglong2 va = xjv[0];
        ulonglong2 vb = xjv[1];
        ulonglong2 vc = xjv[2];
        ulonglong2 vd = xjv[3];

        unsigned long long dp0, dp1;
        MUL2(dp0, xi[0], va.x);
        MUL2(dp1, xi[1], va.y);
        FMA2(dp0, xi[2], vb.x, dp0);
        FMA2(dp1, xi[3], vb.y, dp1);
        FMA2(dp0, xi[4], vc.x, dp0);
        FMA2(dp1, xi[5], vc.y, dp1);
        FMA2(dp0, xi[6], vd.x, dp0);
        FMA2(dp1, xi[7], vd.y, dp1);

        float a0, a1, b0, b1;
        unpack2(dp0, a0, a1);
        unpack2(dp1, b0, b1);
        float dot = (a0 + a1) + (b0 + b1);

        float2 sc = s_sc[jj];
        // targ = log2(2*exp(-d2)) = ai + bj + 2*LOG2E*dot   (clamp dropped: |err|~1e-7)
        float targ = fmaf(dot, 2.0f * LOG2E, ai + sc.x);
        float w;
        asm("ex2.approx.f32 %0, %1;" : "=f"(w) : "f"(targ));
        w = (ci > sc.y) ? w : 0.0f;

        unsigned long long w2 = pack2(w, w);
        FMA2(acc[0], w2, va.x, acc[0]);
        FMA2(acc[1], w2, va.y, acc[1]);
        FMA2(acc[2], w2, vb.x, acc[2]);
        FMA2(acc[3], w2, vb.y, acc[3]);
        FMA2(acc[4], w2, vc.x, acc[4]);
        FMA2(acc[5], w2, vc.y, acc[5]);
        FMA2(acc[6], w2, vd.x, acc[6]);
        FMA2(acc[7], w2, vd.y, acc[7]);
        wsum += w;
    }

    float* base = g_part + (size_t)blockIdx.y * 17 * NTOT;
#pragma unroll
    for (int q = 0; q < 8; ++q) {
        float lo, hi;
        unpack2(acc[q], lo, hi);
        base[(2 * q) * NTOT + i]     = lo;
        base[(2 * q + 1) * NTOT + i] = hi;
    }
    base[16 * NTOT + i] = wsum;
}

// ---------------- update: reduce valid partials, walk, clip, mix, recompute ----------------
__global__ void update_kernel(float* __restrict__ xout,
                              const float* __restrict__ noise_step,
                              float alpha, int do_mix) {
    int r = blockIdx.x * blockDim.x + threadIdx.x;   // sorted slot
    if (r >= NTOT) return;
    int s  = r / POP;
    int rl = r % POP;
    int bi = rl / IBLOCK;
    int nch = ((bi + 1) * IBLOCK - 1) / JCHUNK + 1;  // chunks that actually ran

    int p = g_perm[r];                 // original index within species
    int orig = s * POP + p;
    int ds = (do_mix && p >= POP / 2) ? ((s + 1) & (SPECIES - 1)) : s;
    int didx = ds * POP + p;

    float ws = 0.0f;
    for (int k = 0; k < nch; ++k)
        ws += g_part[((size_t)k * 17 + 16) * NTOT + r];

    float sq = 0.0f;
    float cost = 10.0f * (float)DIM;
    const float scale = alpha * (UBV - LBV);

#pragma unroll
    for (int d = 0; d < DIM; ++d) {
        float a = 0.0f;
        for (int k = 0; k < nch; ++k)
            a += g_part[((size_t)k * 17 + d) * NTOT + r];
        float xv = g_xS[r * DIM + d];
        float rw = scale * (noise_step[orig * DIM + d] - 0.5f);
        float xn = xv + (a - ws * xv) + rw;
        xn = fminf(fmaxf(xn, LBV), UBV);
        xout[didx * DIM + d] = xn;
        sq = fmaf(xn, xn, sq);
        cost += xn * xn - 10.0f * cosf(6.283185307179586f * xn);
    }
    g_sq[didx] = sq;
    g_cost[didx] = cost;
}

// ---------------- launch ----------------
extern "C" void kernel_launch(void* const* d_in, const int* in_sizes, int n_in,
                              void* d_out, int out_size) {
    const float* fireflies = (const float*)d_in[0];
    const float* noise     = (const float*)d_in[1];
    float* out = (float*)d_out;

    float* xA;
    cudaGetSymbolAddress((void**)&xA, g_xA);

    dim3 pw_grid(POP / IBLOCK, JSPLIT, SPECIES);
    int up_blocks = NTOT / 256;

    prep_kernel<<<up_blocks, 256>>>(fireflies);

    double alpha = 0.1;
    for (int step = 0; step < NSTEPS; ++step) {
        sort_kernel<<<SPECIES, 1024>>>();
        gather_kernel<<<up_blocks, 256>>>();
        pairwise_kernel<<<pw_grid, IBLOCK>>>();
        float* dst = (step == NSTEPS - 1) ? out : xA;
        const float* nz = noise + (size_t)step * NTOT * DIM;
        int do_mix = (step % 25 == 0) ? 1 : 0;
        update_kernel<<<up_blocks, 256>>>(dst, nz, (float)alpha, do_mix);
        alpha *= 0.995;
    }
}

// round 3
// speedup vs baseline: 1.1323x; 1.1059x over previous
#include <cuda_runtime.h>

#define SPECIES 4
#define POP     4096
#define DIM     16
#define NTOT    (SPECIES * POP)      // 16384
#define IBLOCK  128
#define JCHUNK  256
#define JSPLIT  (POP / JCHUNK)       // 16
#define NSTEPS  4

#define LBV (-4.0f)
#define UBV (4.0f)
#define LOG2E 1.44269504088896340736f

// ---------------- device scratch ----------------
__device__ float  g_xA[NTOT * DIM];     // original-order positions
__device__ float  g_xS[NTOT * DIM];     // sorted-order positions
__device__ float  g_sq[NTOT];           // |x|^2, original order
__device__ float  g_cost[NTOT];         // cost, original order
__device__ int    g_perm[NTOT];         // sorted slot -> original p (within species)
__device__ float2 g_scS[NTOT];          // sorted: (-LOG2E*sq, cost)
__device__ float  g_part[JSPLIT * 17 * NTOT];

// ---------------- f32x2 helpers ----------------
__device__ __forceinline__ unsigned long long pack2(float lo, float hi) {
    unsigned long long r;
    asm("mov.b64 %0, {%1, %2};" : "=l"(r) : "f"(lo), "f"(hi));
    return r;
}
__device__ __forceinline__ void unpack2(unsigned long long v, float& lo, float& hi) {
    asm("mov.b64 {%0, %1}, %2;" : "=f"(lo), "=f"(hi) : "l"(v));
}
#define FMA2(d, a, b, c) \
    asm("fma.rn.f32x2 %0, %1, %2, %3;" : "=l"(d) : "l"(a), "l"(b), "l"(c))
#define MUL2(d, a, b) \
    asm("mul.rn.f32x2 %0, %1, %2;" : "=l"(d) : "l"(a), "l"(b))
#define ADD2(d, a, b) \
    asm("add.rn.f32x2 %0, %1, %2;" : "=l"(d) : "l"(a), "l"(b))

// ---------------- prep ----------------
__global__ void prep_kernel(const float* __restrict__ fireflies) {
    int idx = blockIdx.x * blockDim.x + threadIdx.x;
    if (idx >= NTOT) return;
    const float4* src = reinterpret_cast<const float4*>(fireflies + idx * DIM);
    float4* dst = reinterpret_cast<float4*>(g_xA + idx * DIM);
    float sq = 0.0f;
    float cost = 10.0f * (float)DIM;
#pragma unroll
    for (int q = 0; q < 4; ++q) {
        float4 v = src[q];
        dst[q] = v;
        float xs[4] = {v.x, v.y, v.z, v.w};
#pragma unroll
        for (int e = 0; e < 4; ++e) {
            float xv = xs[e];
            sq = fmaf(xv, xv, sq);
            cost += xv * xv - 10.0f * cosf(6.283185307179586f * xv);
        }
    }
    g_sq[idx] = sq;
    g_cost[idx] = cost;
}

// ---------------- fused sort (bitonic, u64 packed) + gather ----------------
__global__ __launch_bounds__(1024) void sortgather_kernel() {
    __shared__ unsigned long long key[POP];   // 32 KB: (cost_bits<<32)|idx
    const int s = blockIdx.x;

#pragma unroll
    for (int t = threadIdx.x; t < POP; t += 1024) {
        unsigned int cb = __float_as_uint(g_cost[s * POP + t]);  // cost >= 0
        key[t] = ((unsigned long long)cb << 32) | (unsigned int)t;
    }
    __syncthreads();

    for (int k = 2; k <= POP; k <<= 1) {
        for (int j = k >> 1; j > 0; j >>= 1) {
#pragma unroll
            for (int p = threadIdx.x; p < POP / 2; p += 1024) {
                int ii  = ((p & ~(j - 1)) << 1) | (p & (j - 1));
                int ixj = ii | j;
                bool up = ((ii & k) == 0);
                unsigned long long a = key[ii], b = key[ixj];
                if ((a > b) == up) { key[ii] = b; key[ixj] = a; }
            }
            __syncthreads();
        }
    }

    // gather into sorted order
#pragma unroll
    for (int t = threadIdx.x; t < POP; t += 1024) {
        unsigned long long kv = key[t];
        int p = (int)(kv & 0xffffffffu);
        int orig = s * POP + p;
        int r = s * POP + t;
        g_perm[r] = p;
        float cost = __uint_as_float((unsigned int)(kv >> 32));
        g_scS[r] = make_float2(-LOG2E * g_sq[orig], cost);
        const float4* src = reinterpret_cast<const float4*>(g_xA + orig * DIM);
        float4* dst = reinterpret_cast<float4*>(g_xS + r * DIM);
#pragma unroll
        for (int q = 0; q < 4; ++q) dst[q] = src[q];
    }
}

// ---------------- pairwise, lower-triangle blocks, reg double-buffered ----------------
__global__ __launch_bounds__(IBLOCK) void pairwise_kernel() {
    if (blockIdx.y * JCHUNK > blockIdx.x * IBLOCK + (IBLOCK - 1)) return;

    __shared__ float  s_x[JCHUNK * DIM];   // 16 KB
    __shared__ float2 s_sc[JCHUNK];        // 2 KB

    const int s  = blockIdx.z;
    const int i  = s * POP + blockIdx.x * IBLOCK + threadIdx.x;
    const int j0 = s * POP + blockIdx.y * JCHUNK;

    {
        const float4* src = reinterpret_cast<const float4*>(g_xS + j0 * DIM);
        float4* dst = reinterpret_cast<float4*>(s_x);
#pragma unroll
        for (int t = threadIdx.x; t < (JCHUNK * DIM) / 4; t += IBLOCK)
            dst[t] = src[t];
#pragma unroll
        for (int t = threadIdx.x; t < JCHUNK; t += IBLOCK)
            s_sc[t] = g_scS[j0 + t];
    }
    __syncthreads();

    unsigned long long xi[8];
    {
        const ulonglong2* xp = reinterpret_cast<const ulonglong2*>(g_xS + i * DIM);
#pragma unroll
        for (int q = 0; q < 4; ++q) {
            ulonglong2 v = xp[q];
            xi[2 * q]     = v.x;
            xi[2 * q + 1] = v.y;
        }
    }
    const float2 sci = g_scS[i];
    const float ai = 1.0f + sci.x;   // log2(2) - LOG2E*sq_i
    const float ci = sci.y;

    unsigned long long acc[8];
    const unsigned long long zero2 = pack2(0.0f, 0.0f);
#pragma unroll
    for (int q = 0; q < 8; ++q) acc[q] = zero2;
    float wsum = 0.0f;

    // prefetch j=0
    unsigned long long cur[4][2];
    {
        const ulonglong2* xjv = reinterpret_cast<const ulonglong2*>(s_x);
#pragma unroll
        for (int q = 0; q < 4; ++q) {
            ulonglong2 v = xjv[q];
            cur[q][0] = v.x; cur[q][1] = v.y;
        }
    }
    float2 scj = s_sc[0];

#pragma unroll 4
    for (int jj = 0; jj < JCHUNK; ++jj) {
        // prefetch next j (wraps harmlessly on last iter)
        int jn = (jj + 1) & (JCHUNK - 1);
        unsigned long long nxt[4][2];
        const ulonglong2* xjv = reinterpret_cast<const ulonglong2*>(s_x + jn * DIM);
#pragma unroll
        for (int q = 0; q < 4; ++q) {
            ulonglong2 v = xjv[q];
            nxt[q][0] = v.x; nxt[q][1] = v.y;
        }
        float2 scn = s_sc[jn];

        unsigned long long dp0, dp1;
        MUL2(dp0, xi[0], cur[0][0]);
        MUL2(dp1, xi[1], cur[0][1]);
        FMA2(dp0, xi[2], cur[1][0], dp0);
        FMA2(dp1, xi[3], cur[1][1], dp1);
        FMA2(dp0, xi[4], cur[2][0], dp0);
        FMA2(dp1, xi[5], cur[2][1], dp1);
        FMA2(dp0, xi[6], cur[3][0], dp0);
        FMA2(dp1, xi[7], cur[3][1], dp1);

        unsigned long long dps;
        ADD2(dps, dp0, dp1);
        float a0, a1;
        unpack2(dps, a0, a1);
        float dot = a0 + a1;

        float targ = fmaf(dot, 2.0f * LOG2E, ai + scj.x);
        float w;
        asm("ex2.approx.f32 %0, %1;" : "=f"(w) : "f"(targ));
        w = (ci > scj.y) ? w : 0.0f;

        unsigned long long w2 = pack2(w, w);
        FMA2(acc[0], w2, cur[0][0], acc[0]);
        FMA2(acc[1], w2, cur[0][1], acc[1]);
        FMA2(acc[2], w2, cur[1][0], acc[2]);
        FMA2(acc[3], w2, cur[1][1], acc[3]);
        FMA2(acc[4], w2, cur[2][0], acc[4]);
        FMA2(acc[5], w2, cur[2][1], acc[5]);
        FMA2(acc[6], w2, cur[3][0], acc[6]);
        FMA2(acc[7], w2, cur[3][1], acc[7]);
        wsum += w;

#pragma unroll
        for (int q = 0; q < 4; ++q) {
            cur[q][0] = nxt[q][0]; cur[q][1] = nxt[q][1];
        }
        scj = scn;
    }

    float* base = g_part + (size_t)blockIdx.y * 17 * NTOT;
#pragma unroll
    for (int q = 0; q < 8; ++q) {
        float lo, hi;
        unpack2(acc[q], lo, hi);
        base[(2 * q) * NTOT + i]     = lo;
        base[(2 * q + 1) * NTOT + i] = hi;
    }
    base[16 * NTOT + i] = wsum;
}

// ---------------- update ----------------
__global__ void update_kernel(float* __restrict__ xout,
                              const float* __restrict__ noise_step,
                              float alpha, int do_mix) {
    int r = blockIdx.x * blockDim.x + threadIdx.x;   // sorted slot
    if (r >= NTOT) return;
    int s  = r / POP;
    int rl = r % POP;
    int bi = rl / IBLOCK;
    int nch = ((bi + 1) * IBLOCK - 1) / JCHUNK + 1;

    int p = g_perm[r];
    int orig = s * POP + p;
    int ds = (do_mix && p >= POP / 2) ? ((s + 1) & (SPECIES - 1)) : s;
    int didx = ds * POP + p;

    float ws = 0.0f;
    for (int k = 0; k < nch; ++k)
        ws += g_part[((size_t)k * 17 + 16) * NTOT + r];

    float a[DIM];
#pragma unroll
    for (int d = 0; d < DIM; ++d) a[d] = 0.0f;
    for (int k = 0; k < nch; ++k) {
        const float* pk = g_part + (size_t)k * 17 * NTOT + r;
#pragma unroll
        for (int d = 0; d < DIM; ++d) a[d] += pk[(size_t)d * NTOT];
    }

    const float scale = alpha * (UBV - LBV);
    float sq = 0.0f;
    float cost = 10.0f * (float)DIM;
    const float4* xv4 = reinterpret_cast<const float4*>(g_xS + r * DIM);
    const float4* nz4 = reinterpret_cast<const float4*>(noise_step + (size_t)orig * DIM);
    float4* out4 = reinterpret_cast<float4*>(xout + (size_t)didx * DIM);

#pragma unroll
    for (int q = 0; q < 4; ++q) {
        float4 xv = xv4[q];
        float4 nz = nz4[q];
        float xin[4] = {xv.x, xv.y, xv.z, xv.w};
        float nzs[4] = {nz.x, nz.y, nz.z, nz.w};
        float xo[4];
#pragma unroll
        for (int e = 0; e < 4; ++e) {
            float xn = xin[e] + (a[q * 4 + e] - ws * xin[e])
                     + scale * (nzs[e] - 0.5f);
            xn = fminf(fmaxf(xn, LBV), UBV);
            xo[e] = xn;
            sq = fmaf(xn, xn, sq);
            cost += xn * xn - 10.0f * cosf(6.283185307179586f * xn);
        }
        out4[q] = make_float4(xo[0], xo[1], xo[2], xo[3]);
    }
    g_sq[didx] = sq;
    g_cost[didx] = cost;
}

// ---------------- launch ----------------
extern "C" void kernel_launch(void* const* d_in, const int* in_sizes, int n_in,
                              void* d_out, int out_size) {
    const float* fireflies = (const float*)d_in[0];
    const float* noise     = (const float*)d_in[1];
    float* out = (float*)d_out;

    float* xA;
    cudaGetSymbolAddress((void**)&xA, g_xA);

    dim3 pw_grid(POP / IBLOCK, JSPLIT, SPECIES);
    int up_blocks = NTOT / 256;

    prep_kernel<<<up_blocks, 256>>>(fireflies);

    double alpha = 0.1;
    for (int step = 0; step < NSTEPS; ++step) {
        sortgather_kernel<<<SPECIES, 1024>>>();
        pairwise_kernel<<<pw_grid, IBLOCK>>>();
        float* dst = (step == NSTEPS - 1) ? out : xA;
        const float* nz = noise + (size_t)step * NTOT * DIM;
        int do_mix = (step % 25 == 0) ? 1 : 0;
        update_kernel<<<up_blocks, 256>>>(dst, nz, (float)alpha, do_mix);
        alpha *= 0.995;
    }
}

// round 4
// speedup vs baseline: 1.3564x; 1.1979x over previous
#include <cuda_runtime.h>

#define SPECIES 4
#define POP     4096
#define DIM     16
#define NTOT    (SPECIES * POP)      // 16384
#define ISPAN   256                  // i-rows per pairwise block (128 thr x 2)
#define JCHUNK  256
#define JSPLIT  (POP / JCHUNK)       // 16
#define NSTEPS  4

#define LBV (-4.0f)
#define UBV (4.0f)
#define LOG2E 1.44269504088896340736f

// ---------------- device scratch ----------------
__device__ float  g_xA[NTOT * DIM];     // original-order positions
__device__ float  g_xS[NTOT * DIM];     // sorted-order positions
__device__ float  g_sq[NTOT];           // |x|^2, original order
__device__ float  g_cost[NTOT];         // cost, original order
__device__ int    g_perm[NTOT];         // sorted slot -> original p (within species)
__device__ float2 g_scS[NTOT];          // sorted: (-LOG2E*sq, cost)
__device__ float  g_part[JSPLIT * 17 * NTOT];

// ---------------- f32x2 helpers ----------------
__device__ __forceinline__ unsigned long long pack2(float lo, float hi) {
    unsigned long long r;
    asm("mov.b64 %0, {%1, %2};" : "=l"(r) : "f"(lo), "f"(hi));
    return r;
}
__device__ __forceinline__ void unpack2(unsigned long long v, float& lo, float& hi) {
    asm("mov.b64 {%0, %1}, %2;" : "=f"(lo), "=f"(hi) : "l"(v));
}
#define FMA2(d, a, b, c) \
    asm("fma.rn.f32x2 %0, %1, %2, %3;" : "=l"(d) : "l"(a), "l"(b), "l"(c))
#define MUL2(d, a, b) \
    asm("mul.rn.f32x2 %0, %1, %2;" : "=l"(d) : "l"(a), "l"(b))
#define ADD2(d, a, b) \
    asm("add.rn.f32x2 %0, %1, %2;" : "=l"(d) : "l"(a), "l"(b))

// ---------------- prep ----------------
__global__ void prep_kernel(const float* __restrict__ fireflies) {
    int idx = blockIdx.x * blockDim.x + threadIdx.x;
    if (idx >= NTOT) return;
    const float4* src = reinterpret_cast<const float4*>(fireflies + idx * DIM);
    float4* dst = reinterpret_cast<float4*>(g_xA + idx * DIM);
    float sq = 0.0f;
    float cost = 10.0f * (float)DIM;
#pragma unroll
    for (int q = 0; q < 4; ++q) {
        float4 v = src[q];
        dst[q] = v;
        float xs[4] = {v.x, v.y, v.z, v.w};
#pragma unroll
        for (int e = 0; e < 4; ++e) {
            float xv = xs[e];
            sq = fmaf(xv, xv, sq);
            cost += xv * xv - 10.0f * cosf(6.283185307179586f * xv);
        }
    }
    g_sq[idx] = sq;
    g_cost[idx] = cost;
}

// ---------------- sort (bitonic, u64, warp-register tail passes) + gather ----------------
__device__ __forceinline__ unsigned long long ce_keep(unsigned long long v,
                                                      unsigned long long o,
                                                      bool keepmin) {
    return ((v < o) == keepmin) ? v : o;
}

__global__ __launch_bounds__(1024) void sortgather_kernel() {
    __shared__ unsigned long long key[POP];   // 32 KB
    const int s    = blockIdx.x;
    const int lane = threadIdx.x & 31;
    const int warp = threadIdx.x >> 5;
    const int ebase = warp * 128 + lane;      // warp owns 128 contiguous elements

    // load + monotone key pack + initial register session (k = 2..16)
    unsigned long long v[4];
#pragma unroll
    for (int q = 0; q < 4; ++q) {
        int e = ebase + q * 32;
        unsigned int cb = __float_as_uint(g_cost[s * POP + e]);
        cb = (cb & 0x80000000u) ? ~cb : (cb | 0x80000000u);   // order-preserving
        v[q] = ((unsigned long long)cb << 32) | (unsigned int)e;
    }
#pragma unroll
    for (int k = 2; k <= 16; k <<= 1) {
#pragma unroll
        for (int j = 16; j > 0; j >>= 1) {
            if (j >= k) continue;
#pragma unroll
            for (int q = 0; q < 4; ++q) {
                unsigned long long o = __shfl_xor_sync(0xffffffffu, v[q], j);
                int e = ebase + q * 32;
                bool keepmin = (((e & k) == 0) == ((lane & j) == 0));
                v[q] = ce_keep(v[q], o, keepmin);
            }
        }
    }
#pragma unroll
    for (int q = 0; q < 4; ++q) key[ebase + q * 32] = v[q];
    __syncthreads();

    for (int k = 32; k <= POP; k <<= 1) {
        // cross-warp passes in smem
        for (int j = k >> 1; j >= 32; j >>= 1) {
#pragma unroll
            for (int p = threadIdx.x; p < POP / 2; p += 1024) {
                int ii  = ((p & ~(j - 1)) << 1) | (p & (j - 1));
                int ixj = ii | j;
                bool up = ((ii & k) == 0);
                unsigned long long a = key[ii], b = key[ixj];
                if ((a > b) == up) { key[ii] = b; key[ixj] = a; }
            }
            __syncthreads();
        }
        // intra-warp passes j=16..1 in registers
#pragma unroll
        for (int q = 0; q < 4; ++q) v[q] = key[ebase + q * 32];
#pragma unroll
        for (int j = 16; j > 0; j >>= 1) {
#pragma unroll
            for (int q = 0; q < 4; ++q) {
                unsigned long long o = __shfl_xor_sync(0xffffffffu, v[q], j);
                int e = ebase + q * 32;
                bool keepmin = (((e & k) == 0) == ((lane & j) == 0));
                v[q] = ce_keep(v[q], o, keepmin);
            }
        }
#pragma unroll
        for (int q = 0; q < 4; ++q) key[ebase + q * 32] = v[q];
        __syncthreads();
    }

    // gather into sorted order
#pragma unroll
    for (int t = threadIdx.x; t < POP; t += 1024) {
        int p = (int)(key[t] & 0xffffffffu);
        int orig = s * POP + p;
        int r = s * POP + t;
        g_perm[r] = p;
        g_scS[r] = make_float2(-LOG2E * g_sq[orig], g_cost[orig]);
        const float4* src = reinterpret_cast<const float4*>(g_xA + orig * DIM);
        float4* dst = reinterpret_cast<float4*>(g_xS + r * DIM);
#pragma unroll
        for (int q = 0; q < 4; ++q) dst[q] = src[q];
    }
}

// ---------------- pairwise: 2 i-rows per thread, lower-triangle blocks ----------------
// grid: (POP/ISPAN, JSPLIT, SPECIES), block: 128
__global__ __launch_bounds__(128, 4) void pairwise_kernel() {
    if (blockIdx.y * JCHUNK > blockIdx.x * ISPAN + (ISPAN - 1)) return;

    __shared__ float  s_x[JCHUNK * DIM];   // 16 KB
    __shared__ float2 s_sc[JCHUNK];        // 2 KB

    const int s  = blockIdx.z;
    const int i0 = s * POP + blockIdx.x * ISPAN + threadIdx.x;
    const int i1 = i0 + 128;
    const int j0 = s * POP + blockIdx.y * JCHUNK;

    {
        const float4* src = reinterpret_cast<const float4*>(g_xS + j0 * DIM);
        float4* dst = reinterpret_cast<float4*>(s_x);
#pragma unroll
        for (int t = threadIdx.x; t < (JCHUNK * DIM) / 4; t += 128)
            dst[t] = src[t];
#pragma unroll
        for (int t = threadIdx.x; t < JCHUNK; t += 128)
            s_sc[t] = g_scS[j0 + t];
    }
    __syncthreads();

    unsigned long long xi0[8], xi1[8];
    {
        const ulonglong2* xp0 = reinterpret_cast<const ulonglong2*>(g_xS + i0 * DIM);
        const ulonglong2* xp1 = reinterpret_cast<const ulonglong2*>(g_xS + i1 * DIM);
#pragma unroll
        for (int q = 0; q < 4; ++q) {
            ulonglong2 v0 = xp0[q];
            ulonglong2 v1 = xp1[q];
            xi0[2 * q] = v0.x; xi0[2 * q + 1] = v0.y;
            xi1[2 * q] = v1.x; xi1[2 * q + 1] = v1.y;
        }
    }
    const float2 sci0 = g_scS[i0];
    const float2 sci1 = g_scS[i1];
    const float ai0 = 1.0f + sci0.x, ci0 = sci0.y;
    const float ai1 = 1.0f + sci1.x, ci1 = sci1.y;

    unsigned long long acc0[8], acc1[8];
    const unsigned long long zero2 = pack2(0.0f, 0.0f);
#pragma unroll
    for (int q = 0; q < 8; ++q) { acc0[q] = zero2; acc1[q] = zero2; }
    float ws0 = 0.0f, ws1 = 0.0f;

#pragma unroll 2
    for (int jj = 0; jj < JCHUNK; ++jj) {
        const ulonglong2* xjv = reinterpret_cast<const ulonglong2*>(s_x + jj * DIM);
        ulonglong2 va = xjv[0];
        ulonglong2 vb = xjv[1];
        ulonglong2 vc = xjv[2];
        ulonglong2 vd = xjv[3];
        float2 scj = s_sc[jj];

        unsigned long long pA, pB, qA, qB;
        MUL2(pA, xi0[0], va.x);  MUL2(pB, xi0[1], va.y);
        MUL2(qA, xi1[0], va.x);  MUL2(qB, xi1[1], va.y);
        FMA2(pA, xi0[2], vb.x, pA);  FMA2(pB, xi0[3], vb.y, pB);
        FMA2(qA, xi1[2], vb.x, qA);  FMA2(qB, xi1[3], vb.y, qB);
        FMA2(pA, xi0[4], vc.x, pA);  FMA2(pB, xi0[5], vc.y, pB);
        FMA2(qA, xi1[4], vc.x, qA);  FMA2(qB, xi1[5], vc.y, qB);
        FMA2(pA, xi0[6], vd.x, pA);  FMA2(pB, xi0[7], vd.y, pB);
        FMA2(qA, xi1[6], vd.x, qA);  FMA2(qB, xi1[7], vd.y, qB);

        unsigned long long sp, sq2;
        ADD2(sp, pA, pB);
        ADD2(sq2, qA, qB);
        float p0, p1, q0, q1;
        unpack2(sp, p0, p1);
        unpack2(sq2, q0, q1);
        float d0 = p0 + p1;
        float d1 = q0 + q1;

        float t0 = fmaf(d0, 2.0f * LOG2E, ai0 + scj.x);
        float t1 = fmaf(d1, 2.0f * LOG2E, ai1 + scj.x);
        float w0, w1;
        asm("ex2.approx.f32 %0, %1;" : "=f"(w0) : "f"(t0));
        asm("ex2.approx.f32 %0, %1;" : "=f"(w1) : "f"(t1));
        w0 = (ci0 > scj.y) ? w0 : 0.0f;
        w1 = (ci1 > scj.y) ? w1 : 0.0f;

        unsigned long long w20 = pack2(w0, w0);
        unsigned long long w21 = pack2(w1, w1);
        FMA2(acc0[0], w20, va.x, acc0[0]);  FMA2(acc1[0], w21, va.x, acc1[0]);
        FMA2(acc0[1], w20, va.y, acc0[1]);  FMA2(acc1[1], w21, va.y, acc1[1]);
        FMA2(acc0[2], w20, vb.x, acc0[2]);  FMA2(acc1[2], w21, vb.x, acc1[2]);
        FMA2(acc0[3], w20, vb.y, acc0[3]);  FMA2(acc1[3], w21, vb.y, acc1[3]);
        FMA2(acc0[4], w20, vc.x, acc0[4]);  FMA2(acc1[4], w21, vc.x, acc1[4]);
        FMA2(acc0[5], w20, vc.y, acc0[5]);  FMA2(acc1[5], w21, vc.y, acc1[5]);
        FMA2(acc0[6], w20, vd.x, acc0[6]);  FMA2(acc1[6], w21, vd.x, acc1[6]);
        FMA2(acc0[7], w20, vd.y, acc0[7]);  FMA2(acc1[7], w21, vd.y, acc1[7]);
        ws0 += w0;
        ws1 += w1;
    }

    float* base = g_part + (size_t)blockIdx.y * 17 * NTOT;
#pragma unroll
    for (int q = 0; q < 8; ++q) {
        float lo, hi;
        unpack2(acc0[q], lo, hi);
        base[(2 * q) * NTOT + i0]     = lo;
        base[(2 * q + 1) * NTOT + i0] = hi;
        unpack2(acc1[q], lo, hi);
        base[(2 * q) * NTOT + i1]     = lo;
        base[(2 * q + 1) * NTOT + i1] = hi;
    }
    base[16 * NTOT + i0] = ws0;
    base[16 * NTOT + i1] = ws1;
}

// ---------------- update: thread per (firefly, 4-dim group) ----------------
__global__ __launch_bounds__(256) void update_kernel(float* __restrict__ xout,
                                                     const float* __restrict__ noise_step,
                                                     float alpha, int do_mix) {
    int gid = blockIdx.x * 256 + threadIdx.x;   // 4*NTOT threads
    int r = gid >> 2;                            // sorted slot
    int q = gid & 3;                             // dim quad
    int s  = r / POP;
    int rl = r % POP;
    int bi = rl / ISPAN;
    int nch = ((bi + 1) * ISPAN - 1) / JCHUNK + 1;

    int p = g_perm[r];
    int orig = s * POP + p;
    int ds = (do_mix && p >= POP / 2) ? ((s + 1) & (SPECIES - 1)) : s;
    int didx = ds * POP + p;

    float ws = 0.0f;
    float a[4] = {0.0f, 0.0f, 0.0f, 0.0f};
    for (int k = 0; k < nch; ++k) {
        const float* pk = g_part + (size_t)k * 17 * NTOT + r;
        ws += pk[(size_t)16 * NTOT];
#pragma unroll
        for (int e = 0; e < 4; ++e)
            a[e] += pk[(size_t)(4 * q + e) * NTOT];
    }

    float4 xv = *reinterpret_cast<const float4*>(g_xS + (size_t)r * DIM + 4 * q);
    float4 nz = *reinterpret_cast<const float4*>(noise_step + (size_t)orig * DIM + 4 * q);
    const float scale = alpha * (UBV - LBV);

    float xin[4] = {xv.x, xv.y, xv.z, xv.w};
    float nzs[4] = {nz.x, nz.y, nz.z, nz.w};
    float xo[4];
    float sq = 0.0f, cost = 0.0f;
#pragma unroll
    for (int e = 0; e < 4; ++e) {
        float xn = xin[e] + (a[e] - ws * xin[e]) + scale * (nzs[e] - 0.5f);
        xn = fminf(fmaxf(xn, LBV), UBV);
        xo[e] = xn;
        sq = fmaf(xn, xn, sq);
        cost += xn * xn - 10.0f * cosf(6.283185307179586f * xn);
    }
    *reinterpret_cast<float4*>(xout + (size_t)didx * DIM + 4 * q) =
        make_float4(xo[0], xo[1], xo[2], xo[3]);

    // quad reduction (lanes q=0..3 are consecutive)
    sq   += __shfl_xor_sync(0xffffffffu, sq, 1);
    sq   += __shfl_xor_sync(0xffffffffu, sq, 2);
    cost += __shfl_xor_sync(0xffffffffu, cost, 1);
    cost += __shfl_xor_sync(0xffffffffu, cost, 2);
    if (q == 0) {
        g_sq[didx]   = sq;
        g_cost[didx] = cost + 10.0f * (float)DIM;
    }
}

// ---------------- launch ----------------
extern "C" void kernel_launch(void* const* d_in, const int* in_sizes, int n_in,
                              void* d_out, int out_size) {
    const float* fireflies = (const float*)d_in[0];
    const float* noise     = (const float*)d_in[1];
    float* out = (float*)d_out;

    float* xA;
    cudaGetSymbolAddress((void**)&xA, g_xA);

    dim3 pw_grid(POP / ISPAN, JSPLIT, SPECIES);

    prep_kernel<<<NTOT / 256, 256>>>(fireflies);

    double alpha = 0.1;
    for (int step = 0; step < NSTEPS; ++step) {
        sortgather_kernel<<<SPECIES, 1024>>>();
        pairwise_kernel<<<pw_grid, 128>>>();
        float* dst = (step == NSTEPS - 1) ? out : xA;
        const float* nz = noise + (size_t)step * NTOT * DIM;
        int do_mix = (step % 25 == 0) ? 1 : 0;
        update_kernel<<<NTOT * 4 / 256, 256>>>(dst, nz, (float)alpha, do_mix);
        alpha *= 0.995;
    }
}